// round 17
// baseline (speedup 1.0000x reference)
#include <cuda_runtime.h>
#include <cuda_bf16.h>
#include <cstdint>

#define BSZ    4096
#define ITEMW  10242
#define KT2    10496      // baked K: 128 genre + 2304 director + 8064 actor
#define NSTEP  82
#define NSLOT  10         // 0=genre, 1-2=director, 3-9=actor
#define PCX    64
#define BIMG   9216       // s8 B step image: 64 rows x 144 B (128 k + 16 pad)
#define K1SMEM (3 * BIMG) // 27648 B

// ---------------------------------------------------------------------------
// Device scratch
// ---------------------------------------------------------------------------
__device__ float    g_WT[(size_t)64 * KT2];       // folded weights fp32 [d][k]
__device__ uint32_t g_scaleU[3 * 64];             // per-(field,d) max|w| (float bits)
__device__ __align__(16) int8_t g_WQ[(size_t)NSTEP * BIMG];  // s8 step images
__device__ float g_UF[3528 * 64];
__device__ float g_RF[6 * 64];
__device__ float g_part[(size_t)NSLOT * BSZ * PCX];
__device__ float g_cnt[NSLOT * BSZ];
__device__ float g_X[BSZ * 64], g_Y[BSZ * 64];
__device__ float g_S[BSZ * 8];
__device__ float g_SP[4 * 1024 * 64];
__device__ float g_SP2[4 * 16 * 64];
__device__ float g_U[4 * 64];
__device__ float g_O3[64];
__device__ int   g_ctr3;

// ---------------------------------------------------------------------------
// K0: folds. blk<164: item-side fold -> g_WT fp32 (shifts baked: genre kr=k-1,
// director kr=k-130, actor kr=k-2432; OOR->0) + per-(field,d) max via atomicMax.
// blk>=164: user folds + rate.
// ---------------------------------------------------------------------------
__global__ void __launch_bounds__(256) k0_fold(
    const float* __restrict__ genre_W, const float* __restrict__ director_W,
    const float* __restrict__ actor_W, const float* __restrict__ item_W,
    const float* __restrict__ gender_tab, const float* __restrict__ age_tab,
    const float* __restrict__ occ_tab, const float* __restrict__ area_tab,
    const float* __restrict__ user_W, const float* __restrict__ rate_tab)
{
    __shared__ float sA[64][65];
    __shared__ float sB[64][65];
    int tid = threadIdx.x, d = tid & 63, q = tid >> 6;
    int blk = blockIdx.x;

    if (blk < 164) {
        int kb = blk * 64;
        const float* W; int len, iwo, kr0, f;
        if (blk < 2)       { W = genre_W;    len = 25;   iwo = 64;  kr0 = 1;    f = 0; }
        else if (blk < 38) { W = director_W; len = 2186; iwo = 128; kr0 = 130;  f = 1; }
        else               { W = actor_W;    len = 8030; iwo = 192; kr0 = 2432; f = 2; }

        #pragma unroll
        for (int j = q; j < 64; j += 4) sA[j][d] = item_W[(iwo + j) * 64 + d];
        #pragma unroll
        for (int kk = q; kk < 64; kk += 4) {
            int kr = kb + kk - kr0;
            sB[kk][d] = (kr >= 0 && kr < len) ? W[(size_t)kr * 64 + d] : 0.f;
        }
        __syncthreads();
        float res[16] = {};
        #pragma unroll 4
        for (int j = 0; j < 64; ++j) {
            float a = sA[j][d];
            #pragma unroll
            for (int i = 0; i < 16; ++i) res[i] += sB[q + 4 * i][j] * a;
        }
        __syncthreads();
        float lmax = 0.f;
        #pragma unroll
        for (int i = 0; i < 16; ++i) {
            sB[q + 4 * i][d] = res[i];
            lmax = fmaxf(lmax, fabsf(res[i]));
        }
        sA[q][d] = lmax;
        __syncthreads();
        if (tid < 64) {
            float m = fmaxf(fmaxf(sA[0][tid], sA[1][tid]), fmaxf(sA[2][tid], sA[3][tid]));
            atomicMax(&g_scaleU[f * 64 + tid], __float_as_uint(m));
        }
        for (int j = tid; j < 4096; j += 256) {
            int dd = j >> 6, kc = j & 63;
            g_WT[(size_t)dd * KT2 + kb + kc] = sB[kc][dd];
        }
    } else {
        int rb = (blk - 164) * 32;
        #pragma unroll
        for (int j = q; j < 64; j += 4) sA[j][d] = user_W[(192 + j) * 64 + d];
        for (int j2 = tid; j2 < 32 * 64; j2 += 256) {
            int rr = j2 >> 6, col = j2 & 63, r = rb + rr;
            float v = 0.f;
            if (r < 98)         v = gender_tab[r * 64 + col];
            else if (r < 105)   v = age_tab[(r - 98) * 64 + col];
            else if (r < 126)   v = occ_tab[(r - 105) * 64 + col];
            else if (r < 3528)  v = area_tab[(size_t)(r - 126) * 64 + col];
            else if (r < 3534)  v = rate_tab[(r - 3528) * 64 + col];
            sB[rr][col] = v;
        }
        __syncthreads();
        for (int rr = q; rr < 32; rr += 4) {
            int r = rb + rr;
            if (r >= 3534) continue;
            float v = 0.f;
            if (r >= 126 && r < 3528) {
                #pragma unroll 16
                for (int j = 0; j < 64; ++j) v += sB[rr][j] * sA[j][d];
            } else {
                const float* Wg = (r < 98) ? user_W : (r < 105) ? (user_W + 64 * 64)
                                : (r < 126) ? (user_W + 128 * 64) : item_W;
                #pragma unroll 16
                for (int j = 0; j < 64; ++j) v += sB[rr][j] * Wg[j * 64 + d];
            }
            if (r < 3528) g_UF[(size_t)r * 64 + d] = v;
            else          g_RF[(r - 3528) * 64 + d] = v;
        }
    }
}

// ---------------------------------------------------------------------------
// K0q: quantize g_WT -> per-step s8 images (row stride 144 B).
// ---------------------------------------------------------------------------
__global__ void __launch_bounds__(256) k0_quant()
{
    int s = blockIdx.x;
    for (int j = threadIdx.x; j < 64 * 128; j += 256) {
        int n = j >> 7, k = j & 127;
        int kb = s * 128 + k;
        int f = (kb < 128) ? 0 : (kb < 2432 ? 1 : 2);
        float mx = __uint_as_float(g_scaleU[f * 64 + n]);
        float wv = g_WT[(size_t)n * KT2 + kb];
        int qv = 0;
        if (mx > 0.f) qv = __float2int_rn(wv * (127.f / mx));
        qv = max(-127, min(127, qv));
        g_WQ[(size_t)s * BIMG + n * 144 + k] = (int8_t)qv;
    }
}

// ---------------------------------------------------------------------------
// K1: int8 bits GEMM. M=128, 8 warps m16 x n64. A bits global->reg via int2
// (8-B aligned; ITEMW%4==2 forbids int4!) in s8-mma fragment layout, k32-chunk
// double buffered; B s8 images via cp.async 3-ring, fragments via
// conflict-free LDS.32 (stride 144 -> bank=lane). s32 accumulate, dequant at
// flush. Steps: 0 genre, 1..18 director (base 24+128(s-1)), 19..81 actor
// (base 2212+128(s-19)). Splits: sp0 [0,10) slots 0,1; sp1 [10,19) slot 2;
// sp2..sp8 9 steps each -> slots 3..9. Grid (32,9), 256 thr.
// ---------------------------------------------------------------------------
__device__ __forceinline__ void cp16(uint32_t dst, const void* src) {
    asm volatile("cp.async.cg.shared.global [%0], [%1], 16;\n" :: "r"(dst), "l"(src));
}
__device__ __forceinline__ int stepbase(int s) {
    return (s == 0) ? 0 : (s < 19 ? 24 + (s - 1) * 128 : 2212 + (s - 19) * 128);
}

struct A4 { int e[4]; };
__device__ __forceinline__ uint32_t pack4(const A4& v) {
    return (uint32_t)v.e[0] | ((uint32_t)v.e[1] << 8) |
           ((uint32_t)v.e[2] << 16) | ((uint32_t)v.e[3] << 24);
}

__device__ __forceinline__ void issueB(int s, int tid, uint32_t bbuf)
{
    const char* src = (const char*)g_WQ + (size_t)s * BIMG;
    #pragma unroll
    for (int it = 0; it < 2; ++it) {
        int j = it * 256 + tid;
        cp16(bbuf + j * 16, src + j * 16);
    }
    if (tid < 64) cp16(bbuf + (512 + tid) * 16, src + (512 + tid) * 16);
    asm volatile("cp.async.commit_group;\n" ::: "memory");
}

// load one k32 chunk of A fragments: 4 quads via int2 pairs (8-B aligned)
__device__ __forceinline__ void loadA4(const int* __restrict__ p0, const int* __restrict__ p1,
                                       int c, bool guard, A4 (&B)[4])
{
    if (!guard) {
        #pragma unroll
        for (int t = 0; t < 4; ++t) {
            const int* p = (t & 1) ? p1 : p0;
            int cc = c + ((t >> 1) ? 16 : 0);
            int2 v0 = *(const int2*)(p + cc);
            int2 v1 = *(const int2*)(p + cc + 2);
            B[t].e[0] = v0.x; B[t].e[1] = v0.y; B[t].e[2] = v1.x; B[t].e[3] = v1.y;
        }
    } else {
        #pragma unroll
        for (int t = 0; t < 4; ++t) {
            const int* p = (t & 1) ? p1 : p0;
            int cc = c + ((t >> 1) ? 16 : 0);
            #pragma unroll
            for (int b = 0; b < 4; ++b)
                B[t].e[b] = (cc + b < ITEMW) ? p[cc + b] : 0;
        }
    }
}

__device__ __forceinline__ void consume32(const A4 (&Bf)[4], uint32_t bb, uint32_t bOff,
                                          int ch, int cc, bool masked, int lo, int hi,
                                          int (&acc)[8][4], int& cnt0, int& cnt8)
{
    uint32_t a0 = pack4(Bf[0]), a1 = pack4(Bf[1]);
    uint32_t a2 = pack4(Bf[2]), a3 = pack4(Bf[3]);
    if (masked) {
        #pragma unroll
        for (int b = 0; b < 4; ++b) {
            int cA = cc + b, cB = cc + 16 + b;
            int mA = (cA >= lo) & (cA < hi);
            int mB = (cB >= lo) & (cB < hi);
            cnt0 += mA * Bf[0].e[b] + mB * Bf[2].e[b];
            cnt8 += mA * Bf[1].e[b] + mB * Bf[3].e[b];
        }
    } else {
        #pragma unroll
        for (int b = 0; b < 4; ++b) {
            cnt0 += Bf[0].e[b] + Bf[2].e[b];
            cnt8 += Bf[1].e[b] + Bf[3].e[b];
        }
    }
    uint32_t kb = (uint32_t)(ch * 32);
    #pragma unroll
    for (int nt = 0; nt < 8; ++nt) {
        uint32_t ad = bb + (uint32_t)(nt * 1152) + bOff + kb;
        uint32_t b0, b1;
        asm volatile("ld.shared.b32 %0, [%1];" : "=r"(b0) : "r"(ad));
        asm volatile("ld.shared.b32 %0, [%1];" : "=r"(b1) : "r"(ad + 16));
        asm volatile(
            "mma.sync.aligned.m16n8k32.row.col.s32.s8.s8.s32 "
            "{%0,%1,%2,%3}, {%4,%5,%6,%7}, {%8,%9}, {%0,%1,%2,%3};\n"
            : "+r"(acc[nt][0]), "+r"(acc[nt][1]), "+r"(acc[nt][2]), "+r"(acc[nt][3])
            : "r"(a0), "r"(a1), "r"(a2), "r"(a3), "r"(b0), "r"(b1));
    }
}

__device__ __forceinline__ void flushAC(int (&acc)[8][4], int& c0, int& c8, int slot,
                                        int rt, int lane, int w)
{
    int f = (slot == 0) ? 0 : (slot <= 2 ? 1 : 2);
    int row = rt * 128 + w * 16 + (lane >> 2);
    int tg2 = 2 * (lane & 3);
    float* b0 = g_part + ((size_t)slot * BSZ + row) * PCX;
    float* b8 = b0 + 8 * PCX;
    #pragma unroll
    for (int t = 0; t < 8; ++t) {
        int col = t * 8 + tg2;
        float sc0 = __uint_as_float(g_scaleU[f * 64 + col])     * (1.f / 127.f);
        float sc1 = __uint_as_float(g_scaleU[f * 64 + col + 1]) * (1.f / 127.f);
        b0[col]     = (float)acc[t][0] * sc0;
        b0[col + 1] = (float)acc[t][1] * sc1;
        b8[col]     = (float)acc[t][2] * sc0;
        b8[col + 1] = (float)acc[t][3] * sc1;
        acc[t][0] = acc[t][1] = acc[t][2] = acc[t][3] = 0;
    }
    int s1 = c0, s2 = c8;
    s1 += __shfl_xor_sync(0xffffffffu, s1, 1);
    s1 += __shfl_xor_sync(0xffffffffu, s1, 2);
    s2 += __shfl_xor_sync(0xffffffffu, s2, 1);
    s2 += __shfl_xor_sync(0xffffffffu, s2, 2);
    if ((lane & 3) == 0) {
        g_cnt[slot * BSZ + row]     = (float)s1;
        g_cnt[slot * BSZ + row + 8] = (float)s2;
    }
    c0 = 0; c8 = 0;
}

__global__ void __launch_bounds__(256, 2) k1_gemm(const int* __restrict__ item)
{
    extern __shared__ __align__(16) uint8_t smem[];
    uint32_t sB = (uint32_t)__cvta_generic_to_shared(smem);

    int tid = threadIdx.x, lane = tid & 31, w = tid >> 5;
    int rt = blockIdx.x, sp = blockIdx.y;
    int s0, s1;
    if (sp == 0)      { s0 = 0;  s1 = 10; }
    else if (sp == 1) { s0 = 10; s1 = 19; }
    else              { s0 = 19 + 9 * (sp - 2); s1 = s0 + 9; }

    int q4 = (lane & 3) * 4;
    long row0 = (long)(rt * 128 + w * 16 + (lane >> 2));
    const int* p0 = item + row0 * ITEMW;
    const int* p1 = p0 + (long)8 * ITEMW;
    uint32_t bOff = (uint32_t)((lane >> 2) * 144 + q4);

    int acc[8][4] = {};
    int cnt0 = 0, cnt8 = 0;
    A4 buf[2][4];

    issueB(s0,     tid, sB + (s0 % 3) * BIMG);
    issueB(s0 + 1, tid, sB + ((s0 + 1) % 3) * BIMG);
    loadA4(p0, p1, stepbase(s0) + q4, false, buf[0]);   // s0 never 81

    for (int s = s0; s < s1; ++s) {
        if (s + 1 < s1) { asm volatile("cp.async.wait_group 1;\n" ::: "memory"); }
        else            { asm volatile("cp.async.wait_group 0;\n" ::: "memory"); }
        __syncthreads();
        if (s + 2 < s1) issueB(s + 2, tid, sB + ((s + 2) % 3) * BIMG);

        int base = stepbase(s);
        bool masked = (s <= 1) || (s == 18);
        int lo = (s == 0) ? 1 : 26;
        int hi = (s == 0) ? 26 : 2212;
        uint32_t bb = sB + (s % 3) * BIMG;

        #pragma unroll
        for (int ch = 0; ch < 4; ++ch) {
            int ns = s, nc = ch + 1;
            if (nc == 4) { nc = 0; ns = s + 1; }
            if (ns < s1)
                loadA4(p0, p1, stepbase(ns) + nc * 32 + q4, ns == 81, buf[(ch + 1) & 1]);
            consume32(buf[ch & 1], bb, bOff, ch, base + ch * 32 + q4,
                      masked, lo, hi, acc, cnt0, cnt8);
        }
        if (sp == 0 && s == 0) flushAC(acc, cnt0, cnt8, 0, rt, lane, w);   // genre
    }
    flushAC(acc, cnt0, cnt8, (sp == 0) ? 1 : sp + 1, rt, lane, w);
}

// ---------------------------------------------------------------------------
// K2: finalize x/y/edge + per-row scalars + s-vector partials.
// ---------------------------------------------------------------------------
__global__ void __launch_bounds__(256) k2_finalize(
    const int* __restrict__ user_emb, const int* __restrict__ item,
    const int* __restrict__ edge_emb,
    const float* __restrict__ user_b, const float* __restrict__ item_b,
    const float* __restrict__ edges_tab,
    const float* __restrict__ uu_w, const float* __restrict__ ui_w,
    const float* __restrict__ iu_w, const float* __restrict__ ii_w)
{
    int tid = threadIdx.x, lane = tid & 31, warp = tid >> 5;
    int rr = tid >> 6, d = tid & 63;
    int row = blockIdx.x * 4 + rr;

    float ng = g_part[((size_t)0 * BSZ + row) * PCX + d];
    float nd = g_part[((size_t)1 * BSZ + row) * PCX + d]
             + g_part[((size_t)2 * BSZ + row) * PCX + d];
    float na = 0.f, ca = 0.f;
    #pragma unroll
    for (int t = 3; t < NSLOT; ++t) {
        na += g_part[((size_t)t * BSZ + row) * PCX + d];
        ca += g_cnt[t * BSZ + row];
    }
    float cg = g_cnt[0 * BSZ + row];
    float cd = g_cnt[1 * BSZ + row] + g_cnt[2 * BSZ + row];

    int ri = item[(long)row * ITEMW];
    float y = (g_RF[ri * 64 + d] + ng / cg + nd / cd + na / ca + item_b[d]) * 0.12f;

    int gi = user_emb[row * 4 + 0], ai = user_emb[row * 4 + 1];
    int oi = user_emb[row * 4 + 2], ari = user_emb[row * 4 + 3];
    float x = (g_UF[gi * 64 + d] + g_UF[(98 + ai) * 64 + d] + g_UF[(105 + oi) * 64 + d]
             + g_UF[(size_t)(126 + ari) * 64 + d] + user_b[d]) * 0.12f;
    float e = edges_tab[edge_emb[row] * 64 + d] * 0.12f;

    g_X[row * 64 + d] = x;
    g_Y[row * 64 + d] = y;

    __shared__ float sx[4][64], sy[4][64];
    __shared__ float red[8][6], srow[4][6];
    sx[rr][d] = x; sy[rr][d] = y;

    float xe = x * e, ye = y * e;
    float pr[6] = { xe * uu_w[d], xe * ui_w[d], ye * ui_w[d],
                    ye * ii_w[d], ye * iu_w[d], xe * iu_w[d] };
    #pragma unroll
    for (int o = 16; o; o >>= 1) {
        #pragma unroll
        for (int j = 0; j < 6; ++j) pr[j] += __shfl_xor_sync(0xffffffffu, pr[j], o);
    }
    if (lane == 0) {
        #pragma unroll
        for (int j = 0; j < 6; ++j) red[warp][j] = pr[j];
    }
    __syncthreads();
    if (tid < 24) {
        int r2 = tid / 6, j = tid % 6;
        float v = red[2 * r2][j] + red[2 * r2 + 1][j];
        srow[r2][j] = v;
        g_S[(size_t)(blockIdx.x * 4 + r2) * 8 + j] = v;
    }
    __syncthreads();
    if (tid < 64) {
        float s1 = 0, s2 = 0, s3 = 0, s4 = 0;
        #pragma unroll
        for (int r2 = 0; r2 < 4; ++r2) {
            float xv = sx[r2][tid], yv = sy[r2][tid];
            s1 += srow[r2][0] * xv;
            s2 += srow[r2][2] * yv;
            s3 += srow[r2][3] * yv;
            s4 += srow[r2][5] * xv;
        }
        g_SP[(0 * 1024 + blockIdx.x) * 64 + tid] = s1;
        g_SP[(1 * 1024 + blockIdx.x) * 64 + tid] = s2;
        g_SP[(2 * 1024 + blockIdx.x) * 64 + tid] = s3;
        g_SP[(3 * 1024 + blockIdx.x) * 64 + tid] = s4;
    }
}

// ---------------------------------------------------------------------------
// K3: s-vector reduce; last CTA (atomic election) does u1..u4 + edge branch.
// ---------------------------------------------------------------------------
__global__ void __launch_bounds__(256) k3_reduce(
    const float* __restrict__ uu_W1, const float* __restrict__ ui_W1,
    const float* __restrict__ ii_W1, const float* __restrict__ iu_W1,
    const float* __restrict__ edge_W, const float* __restrict__ edges_tab)
{
    int tid = threadIdx.x, v = tid >> 6, d = tid & 63, b = blockIdx.x;
    float s = 0.f;
    #pragma unroll 8
    for (int i = b * 64; i < b * 64 + 64; ++i)
        s += g_SP[((size_t)v * 1024 + i) * 64 + d];
    g_SP2[(v * 16 + b) * 64 + d] = s;

    __threadfence();
    __shared__ int amlast;
    if (tid == 0) amlast = (atomicAdd(&g_ctr3, 1) == 15) ? 1 : 0;
    __syncthreads();
    if (!amlast) return;

    __shared__ float sq[4][64];
    __shared__ float ev[64];
    float tot = 0.f;
    #pragma unroll
    for (int bb = 0; bb < 16; ++bb) tot += g_SP2[(v * 16 + bb) * 64 + d];
    sq[v][d] = tot;
    if (tid < 64) ev[tid] = edges_tab[tid] * 0.12f;
    __syncthreads();

    const float* W1 = (v == 0) ? uu_W1 : (v == 1) ? ui_W1 : (v == 2) ? ii_W1 : iu_W1;
    float u = 0.f;
    #pragma unroll
    for (int j = 0; j < 64; ++j) u += sq[v][j] * W1[j * 64 + d];
    g_U[v * 64 + d] = u;

    if (tid < 64) {
        float nv = 0.f;
        #pragma unroll
        for (int j = 0; j < 64; ++j) nv += ev[j] * edge_W[j * 64 + tid];
        nv = nv >= 0.f ? nv : 0.01f * nv;
        g_O3[tid] = 0.5f * (nv + ev[tid]);
    }
    if (tid == 0) g_ctr3 = 0;
}

// ---------------------------------------------------------------------------
// K4: final elementwise assembly
// ---------------------------------------------------------------------------
__global__ void __launch_bounds__(256) k4_out(float* __restrict__ out)
{
    int idx = blockIdx.x * 256 + threadIdx.x;
    int r = idx >> 6, d = idx & 63;
    float x_xx   = g_S[(size_t)r * 8 + 0];
    float x_xy_x = g_S[(size_t)r * 8 + 1];
    float y_yy   = g_S[(size_t)r * 8 + 3];
    float y_yx_y = g_S[(size_t)r * 8 + 4];
    float a1 = x_xx * g_U[d];         a1 = a1 >= 0.f ? a1 : 0.01f * a1;
    float a2 = x_xy_x * g_U[64 + d];  a2 = a2 >= 0.f ? a2 : 0.01f * a2;
    float b1 = y_yy * g_U[128 + d];   b1 = b1 >= 0.f ? b1 : 0.01f * b1;
    float b2 = y_yx_y * g_U[192 + d]; b2 = b2 >= 0.f ? b2 : 0.01f * b2;
    out[idx]          = ((a1 + a2) * 0.5f + g_X[idx]) * 0.5f;
    out[262144 + idx] = ((b1 + b2) * 0.5f + g_Y[idx]) * 0.5f;
    out[524288 + idx] = g_O3[d];
}

// ---------------------------------------------------------------------------
// launch (6 kernels)
// ---------------------------------------------------------------------------
extern "C" void kernel_launch(void* const* d_in, const int* in_sizes, int n_in,
                              void* d_out, int out_size)
{
    const int*   user_emb   = (const int*)d_in[0];
    const int*   item_emb   = (const int*)d_in[1];
    const int*   edge_emb   = (const int*)d_in[2];
    const float* gender_tab = (const float*)d_in[3];
    const float* age_tab    = (const float*)d_in[4];
    const float* occ_tab    = (const float*)d_in[5];
    const float* area_tab   = (const float*)d_in[6];
    const float* user_W     = (const float*)d_in[7];
    const float* user_b     = (const float*)d_in[8];
    const float* rate_tab   = (const float*)d_in[9];
    const float* genre_W    = (const float*)d_in[10];
    const float* director_W = (const float*)d_in[11];
    const float* actor_W    = (const float*)d_in[12];
    const float* item_W     = (const float*)d_in[13];
    const float* item_b     = (const float*)d_in[14];
    const float* edges_tab  = (const float*)d_in[15];
    const float* uu_w       = (const float*)d_in[16];
    const float* ui_w       = (const float*)d_in[17];
    const float* iu_w       = (const float*)d_in[18];
    const float* ii_w       = (const float*)d_in[19];
    const float* edge_W     = (const float*)d_in[20];
    const float* uu_W1      = (const float*)d_in[21];
    const float* ui_W1      = (const float*)d_in[22];
    const float* iu_W1      = (const float*)d_in[23];
    const float* ii_W1      = (const float*)d_in[24];
    float* out = (float*)d_out;

    k0_fold<<<275, 256>>>(genre_W, director_W, actor_W, item_W,
                          gender_tab, age_tab, occ_tab, area_tab, user_W, rate_tab);
    k0_quant<<<NSTEP, 256>>>();
    k1_gemm<<<dim3(32, 9), 256, K1SMEM>>>(item_emb);
    k2_finalize<<<1024, 256>>>(user_emb, item_emb, edge_emb, user_b, item_b, edges_tab,
                               uu_w, ui_w, iu_w, ii_w);
    k3_reduce<<<16, 256>>>(uu_W1, ui_W1, ii_W1, iu_W1, edge_W, edges_tab);
    k4_out<<<1024, 256>>>(out);
}